// round 13
// baseline (speedup 1.0000x reference)
#include <cuda_runtime.h>
#include <math.h>

// Problem constants
#define NPATCH     8
#define BINS       256
#define IMG_H      1024
#define IMG_W      1024
#define NBC        48            // B*C = 16*3
#define PH         128           // patch height
#define PW         128           // patch width
#define SEGS       6144          // NBC * PH row-segments per patch
#define CHUNKS     32            // blocks per patch
#define TOTAL_ELEMS 50331648.0   // 16*3*1024*1024

// XLA algsimp folds divide-by-constant -> multiply-by-f32-reciprocal.
__device__ __constant__ float RECIP_N   = 1.0f / 786432.0f;   // 0x35AAAAAB
__device__ __constant__ float RECIP_LN2 = 1.442695040888963f; // fl(1/fl(ln2)) = 0x3FB8AA3B

// Scratch (no allocation allowed in kernel_launch)
__device__ unsigned int g_hist[64 * BINS];
__device__ double       g_psum[64];
__device__ float        g_ent[64];

__global__ void zero_kernel() {
    int i = blockIdx.x * blockDim.x + threadIdx.x;
    if (i < 64 * BINS) g_hist[i] = 0u;
    if (i < 64)        g_psum[i] = 0.0;
}

// One block = (patch, chunk). 256 threads, 8 warps.
// Each warp processes whole 128-float row segments: lane -> float4.
__global__ __launch_bounds__(256)
void hist_kernel(const float* __restrict__ sr, const float* __restrict__ hr) {
    __shared__ unsigned int sh_hist[BINS];
    __shared__ float        sh_psum;

    const int tid = threadIdx.x;
    if (tid < BINS) sh_hist[tid] = 0u;
    if (tid == 0)   sh_psum = 0.0f;
    __syncthreads();

    const int patch = blockIdx.x >> 5;     // 0..63
    const int chunk = blockIdx.x & (CHUNKS - 1);
    const int pr = patch >> 3;             // patch row (height)
    const int pc = patch & 7;              // patch col (width)
    const int warp = tid >> 5;
    const int lane = tid & 31;

    const size_t col = (size_t)pc * PW + (size_t)lane * 4;
    float acc = 0.0f;

    // 6144 segments / 256 warps-per-patch-in-grid = 24 iterations, balanced
    for (int s = chunk * 8 + warp; s < SEGS; s += CHUNKS * 8) {
        const int bc = s >> 7;         // which (b,c) plane
        const int r  = s & 127;        // row within patch
        const size_t base =
            (((size_t)bc * IMG_H) + (size_t)pr * PH + r) * (size_t)IMG_W + col;

        const float4 h  = *reinterpret_cast<const float4*>(hr + base);
        const float4 sv = *reinterpret_cast<const float4*>(sr + base);

        // (h * 255.0f) f32 multiply, truncate toward zero — bit-identical to
        // (patches * 255.0).astype(int32). Values in [0,1) -> bins 0..254.
        int b0 = (int)(h.x * 255.0f);
        int b1 = (int)(h.y * 255.0f);
        int b2 = (int)(h.z * 255.0f);
        int b3 = (int)(h.w * 255.0f);

        atomicAdd(&sh_hist[b0], 1u);
        atomicAdd(&sh_hist[b1], 1u);
        atomicAdd(&sh_hist[b2], 1u);
        atomicAdd(&sh_hist[b3], 1u);

        acc += fabsf(sv.x - h.x) + fabsf(sv.y - h.y)
             + fabsf(sv.z - h.z) + fabsf(sv.w - h.w);
    }

    // warp tree-reduce abs-diff partial
    #pragma unroll
    for (int o = 16; o > 0; o >>= 1)
        acc += __shfl_down_sync(0xffffffffu, acc, o);
    if (lane == 0) atomicAdd(&sh_psum, acc);
    __syncthreads();

    // merge block-private results into globals
    if (tid < BINS) {
        unsigned int c = sh_hist[tid];
        if (c) atomicAdd(&g_hist[patch * BINS + tid], c);
    }
    if (tid == 0) atomicAdd(&g_psum[patch], (double)sh_psum);
}

// Per-element term — algsimp-folded chain (both constant divides -> muls):
//   p    = (f32)c * f32(1/786432)
//   ln   = logf(p)   — nvcc's logf IS libdevice __nv_logf, the exact function
//                      XLA links for lax.log on this container
//   l2   = ln * fl(1/fl(ln2))       (jnp.log2 = log(x)/log(2), folded)
//   term = p * l2                   (separate f32 mul, no FMA)
//   zero-count bins contribute exact 0.0f (the jnp.where arm).
__device__ __forceinline__ float ent_term(unsigned int c) {
    float pf   = __fmul_rn((float)c, RECIP_N);
    float safe = (c > 0u) ? pf : 1.0f;
    float l2   = __fmul_rn(logf(safe), RECIP_LN2);
    return (c > 0u) ? __fmul_rn(pf, l2) : 0.0f;
}

// Candidate A association — XLA:GPU row reduction, row=256, vector_size=1,
// num_threads_x=256 (flat, one element per thread):
//   thread t: acc = 0 + e_t (exact)
//   warp w (bins 32w..32w+31): 5-level shfl.down tree (16,8,4,2,1)
//   8 warp partials -> smem; warp 0: v = lane<8 ? P[lane] : 0.0f, full
//   shfl tree -> ((P0+P4)+(P2+P6))+((P1+P5)+(P3+P7)). Zero-pads exact.
// One block of 256 threads per patch.
__global__ __launch_bounds__(256)
void entropy_kernel() {
    __shared__ float partials[8];
    const int p    = blockIdx.x;       // patch 0..63
    const int t    = threadIdx.x;      // 0..255 = bin
    const int lane = t & 31;
    const int warp = t >> 5;

    float acc = __fadd_rn(0.0f, ent_term(g_hist[p * BINS + t]));

    #pragma unroll
    for (int o = 16; o > 0; o >>= 1)
        acc = __fadd_rn(acc, __shfl_down_sync(0xffffffffu, acc, o));
    if (lane == 0) partials[warp] = acc;
    __syncthreads();

    if (warp == 0) {
        float v = (lane < 8) ? partials[lane] : 0.0f;
        #pragma unroll
        for (int o = 16; o > 0; o >>= 1)
            v = __fadd_rn(v, __shfl_down_sync(0xffffffffu, v, o));
        if (lane == 0) g_ent[p] = -v;   // negate after the sum, like the ref
    }
}

// One block, 64 threads: min/max + weighted loss assembly.
__global__ __launch_bounds__(64)
void loss_kernel(float* __restrict__ out) {
    __shared__ float ent[64];
    const int tid = threadIdx.x;
    ent[tid] = g_ent[tid];
    __syncthreads();

    if (tid == 0) {
        float mn = ent[0], mx = ent[0];
        for (int i = 1; i < 64; i++) {
            mn = fminf(mn, ent[i]);
            mx = fmaxf(mx, ent[i]);
        }
        double loss = 0.0;
        for (int i = 0; i < 64; i++) {
            // weight in f32 exactly as the reference map: (e - mn) / original max
            float w = __fdiv_rn(__fadd_rn(ent[i], -mn), mx);
            loss += (double)w * g_psum[i];
        }
        out[0] = (float)(loss / TOTAL_ELEMS);
    }
}

extern "C" void kernel_launch(void* const* d_in, const int* in_sizes, int n_in,
                              void* d_out, int out_size) {
    const float* sr = (const float*)d_in[0];
    const float* hr = (const float*)d_in[1];
    float* out = (float*)d_out;
    (void)in_sizes; (void)n_in; (void)out_size;

    zero_kernel<<<(64 * BINS + 255) / 256, 256>>>();
    hist_kernel<<<64 * CHUNKS, 256>>>(sr, hr);
    entropy_kernel<<<64, 256>>>();
    loss_kernel<<<1, 64>>>(out);
}